// round 3
// baseline (speedup 1.0000x reference)
#include <cuda_runtime.h>
#include <stdint.h>

#define NDOF_MAX 1000000

// Scratch for u1 (allocation-free rule: static __device__ array)
__device__ float g_u1[NDOF_MAX];

// Kernel A: build u1[bc[i]] = w[i] * u[bc[i]] and zero the output F.
__global__ void prep_kernel(const float* __restrict__ u,
                            const float* __restrict__ w,
                            const int* __restrict__ bc,
                            float* __restrict__ F,
                            int n)
{
    int i = blockIdx.x * blockDim.x + threadIdx.x;
    if (i < n) {
        int b = bc[i];
        g_u1[b] = w[i] * u[b];
        F[i] = 0.0f;   // d_out is poisoned; zero it here (same index space, NDOF)
    }
}

// Kernel B: per-element 8x8 matvec + scatter-add assembly.
// One thread per element.
__global__ void __launch_bounds__(256) assemble_kernel(
    const int* __restrict__ edof,           // [E,8] int32
    const float* __restrict__ ke,           // [E,8,8]
    float* __restrict__ F,                  // [NDOF]
    int E)
{
    int e = blockIdx.x * blockDim.x + threadIdx.x;
    if (e >= E) return;

    // 8 contiguous int32 loads as two int4 (32 B per thread, coalesced)
    const int4* erow = reinterpret_cast<const int4*>(edof + (size_t)e * 8);
    int4 i0 = erow[0];
    int4 i1 = erow[1];
    int idx[8] = { i0.x, i0.y, i0.z, i0.w, i1.x, i1.y, i1.z, i1.w };

    // gather elemental DOF values (L2-resident, 4 MB window)
    float ue[8];
    #pragma unroll
    for (int j = 0; j < 8; j++) ue[j] = __ldg(&g_u1[idx[j]]);

    // 8x8 matvec: 16 float4 loads = 256 B contiguous per thread
    const float4* kv = reinterpret_cast<const float4*>(ke + (size_t)e * 64);
    float s[8];
    #pragma unroll
    for (int i = 0; i < 8; i++) {
        float4 a = kv[i * 2 + 0];
        float4 b = kv[i * 2 + 1];
        s[i] = a.x * ue[0] + a.y * ue[1] + a.z * ue[2] + a.w * ue[3]
             + b.x * ue[4] + b.y * ue[5] + b.z * ue[6] + b.w * ue[7];
    }
    #pragma unroll
    for (int i = 0; i < 8; i++)
        atomicAdd(&F[idx[i]], s[i]);
}

extern "C" void kernel_launch(void* const* d_in, const int* in_sizes, int n_in,
                              void* d_out, int out_size)
{
    const float* u    = (const float*)d_in[0];
    const float* w    = (const float*)d_in[1];
    const int*   bc   = (const int*)d_in[2];
    const int*   edof = (const int*)d_in[3];
    const float* ke   = (const float*)d_in[4];
    float* F = (float*)d_out;

    int ndof = in_sizes[0];            // 2*NNODE
    int E    = in_sizes[3] / 8;        // NELEM

    prep_kernel<<<(ndof + 255) / 256, 256>>>(u, w, bc, F, ndof);
    assemble_kernel<<<(E + 255) / 256, 256>>>(edof, ke, F, E);
}

// round 4
// speedup vs baseline: 1.0296x; 1.0296x over previous
#include <cuda_runtime.h>
#include <stdint.h>

#define NDOF_MAX 1000000

__device__ float g_u1[NDOF_MAX];

// Kernel A (vectorized): u1[bc[i]] = w[i] * u[bc[i]]; F[i] = 0.
// Processes 4 DOFs per thread. NDOF = 1e6 is divisible by 4.
__global__ void prep_kernel(const float* __restrict__ u,
                            const float4* __restrict__ w4,
                            const int4* __restrict__ bc4,
                            float4* __restrict__ F4,
                            int n4)
{
    int i = blockIdx.x * blockDim.x + threadIdx.x;
    if (i < n4) {
        int4 b = bc4[i];
        float4 w = w4[i];
        g_u1[b.x] = w.x * __ldg(&u[b.x]);
        g_u1[b.y] = w.y * __ldg(&u[b.y]);
        g_u1[b.z] = w.z * __ldg(&u[b.z]);
        g_u1[b.w] = w.w * __ldg(&u[b.w]);
        F4[i] = make_float4(0.f, 0.f, 0.f, 0.f);
    }
}

// Kernel B: 2 elements per thread (block-strided), streaming hints on ke/edof.
__global__ void __launch_bounds__(256) assemble_kernel(
    const int* __restrict__ edof,           // [E,8] int32
    const float* __restrict__ ke,           // [E,8,8]
    float* __restrict__ F,                  // [NDOF]
    int E)
{
    const int e0 = blockIdx.x * 512 + threadIdx.x;
    const int e1 = e0 + 256;
    const bool v0 = (e0 < E);
    const bool v1 = (e1 < E);

    int idx0[8], idx1[8];
    float ue0[8], ue1[8];

    // Front-batch index loads (evict-first: pure stream)
    if (v0) {
        const int4* p = reinterpret_cast<const int4*>(edof + (size_t)e0 * 8);
        int4 a = __ldcs(&p[0]), b = __ldcs(&p[1]);
        idx0[0]=a.x; idx0[1]=a.y; idx0[2]=a.z; idx0[3]=a.w;
        idx0[4]=b.x; idx0[5]=b.y; idx0[6]=b.z; idx0[7]=b.w;
    }
    if (v1) {
        const int4* p = reinterpret_cast<const int4*>(edof + (size_t)e1 * 8);
        int4 a = __ldcs(&p[0]), b = __ldcs(&p[1]);
        idx1[0]=a.x; idx1[1]=a.y; idx1[2]=a.z; idx1[3]=a.w;
        idx1[4]=b.x; idx1[5]=b.y; idx1[6]=b.z; idx1[7]=b.w;
    }

    // Front-batch gathers (L2-resident u1)
    if (v0) {
        #pragma unroll
        for (int j = 0; j < 8; j++) ue0[j] = __ldg(&g_u1[idx0[j]]);
    }
    if (v1) {
        #pragma unroll
        for (int j = 0; j < 8; j++) ue1[j] = __ldg(&g_u1[idx1[j]]);
    }

    // Interleaved matvec for both elements (streaming ke loads)
    const float4* kv0 = reinterpret_cast<const float4*>(ke + (size_t)e0 * 64);
    const float4* kv1 = reinterpret_cast<const float4*>(ke + (size_t)e1 * 64);
    float s0[8], s1[8];
    #pragma unroll
    for (int i = 0; i < 8; i++) {
        if (v0) {
            float4 a = __ldcs(&kv0[i * 2 + 0]);
            float4 b = __ldcs(&kv0[i * 2 + 1]);
            s0[i] = a.x*ue0[0] + a.y*ue0[1] + a.z*ue0[2] + a.w*ue0[3]
                  + b.x*ue0[4] + b.y*ue0[5] + b.z*ue0[6] + b.w*ue0[7];
        }
        if (v1) {
            float4 a = __ldcs(&kv1[i * 2 + 0]);
            float4 b = __ldcs(&kv1[i * 2 + 1]);
            s1[i] = a.x*ue1[0] + a.y*ue1[1] + a.z*ue1[2] + a.w*ue1[3]
                  + b.x*ue1[4] + b.y*ue1[5] + b.z*ue1[6] + b.w*ue1[7];
        }
    }

    // Scatter-add (RED, no return)
    if (v0) {
        #pragma unroll
        for (int i = 0; i < 8; i++) atomicAdd(&F[idx0[i]], s0[i]);
    }
    if (v1) {
        #pragma unroll
        for (int i = 0; i < 8; i++) atomicAdd(&F[idx1[i]], s1[i]);
    }
}

extern "C" void kernel_launch(void* const* d_in, const int* in_sizes, int n_in,
                              void* d_out, int out_size)
{
    const float* u    = (const float*)d_in[0];
    const float* w    = (const float*)d_in[1];
    const int*   bc   = (const int*)d_in[2];
    const int*   edof = (const int*)d_in[3];
    const float* ke   = (const float*)d_in[4];
    float* F = (float*)d_out;

    int ndof = in_sizes[0];            // 2*NNODE (divisible by 4)
    int E    = in_sizes[3] / 8;        // NELEM

    int n4 = ndof / 4;
    prep_kernel<<<(n4 + 255) / 256, 256>>>(
        u, (const float4*)w, (const int4*)bc, (float4*)F, n4);

    assemble_kernel<<<(E + 511) / 512, 256>>>(edof, ke, F, E);
}